// round 3
// baseline (speedup 1.0000x reference)
#include <cuda_runtime.h>
#include <math.h>

// Shapes (fixed for this problem)
//  B=8, L=1024, D=1024, H=8, DH=128, BH=64, VOCAB=32000
//  SCALE = (DH//H)^-0.5 = 0.25
//  Output: [8, 2048] f32 layernorm of [maxpool | meanpool]

#define N_B    8
#define N_L    1024
#define N_D    1024
#define N_BH   64
#define N_DH   128
#define SCALE_F 0.25f
#define EPS_F   1e-5f

// ---------------------------------------------------------------------------
// Scratch (static __device__ arrays; no allocation allowed)
// ---------------------------------------------------------------------------
__device__ float g_x[8u * 1024u * 1024u];   // embedded input  [B,L,D]
__device__ float g_q[8u * 1024u * 1024u];   // Q, later reused as r = x + out
__device__ float g_k[8u * 1024u * 1024u];   // K
__device__ float g_v[8u * 1024u * 1024u];   // V
__device__ float g_c[8u * 1024u * 1024u];   // ctx
__device__ float g_s[67108864u];            // scores/probs [64,1024,1024] (256MB)
__device__ float g_nb[8 * 1024];            // -inf mask bias per (batch,key)
__device__ float g_agg[8 * 2048];           // pooled features

// ---------------------------------------------------------------------------
// Block reductions
// ---------------------------------------------------------------------------
__device__ __forceinline__ float blockSum(float v) {
    __shared__ float sh[32];
    int lane = threadIdx.x & 31, wid = threadIdx.x >> 5;
    #pragma unroll
    for (int o = 16; o > 0; o >>= 1) v += __shfl_xor_sync(0xffffffffu, v, o);
    if (lane == 0) sh[wid] = v;
    __syncthreads();
    int nw = blockDim.x >> 5;
    float r = (threadIdx.x < (unsigned)nw) ? sh[threadIdx.x] : 0.0f;
    if (wid == 0) {
        #pragma unroll
        for (int o = 16; o > 0; o >>= 1) r += __shfl_xor_sync(0xffffffffu, r, o);
        if (lane == 0) sh[0] = r;
    }
    __syncthreads();
    float out = sh[0];
    __syncthreads();
    return out;
}

__device__ __forceinline__ float blockMax(float v) {
    __shared__ float sh[32];
    int lane = threadIdx.x & 31, wid = threadIdx.x >> 5;
    #pragma unroll
    for (int o = 16; o > 0; o >>= 1) v = fmaxf(v, __shfl_xor_sync(0xffffffffu, v, o));
    if (lane == 0) sh[wid] = v;
    __syncthreads();
    int nw = blockDim.x >> 5;
    float r = (threadIdx.x < (unsigned)nw) ? sh[threadIdx.x] : -INFINITY;
    if (wid == 0) {
        #pragma unroll
        for (int o = 16; o > 0; o >>= 1) r = fmaxf(r, __shfl_xor_sync(0xffffffffu, r, o));
        if (lane == 0) sh[0] = r;
    }
    __syncthreads();
    float out = sh[0];
    __syncthreads();
    return out;
}

// ---------------------------------------------------------------------------
// Embedding gather: x[row,:] = emb[tok[row],:]   (8192 rows x 1024 f32)
// ---------------------------------------------------------------------------
__global__ void embed_kernel(const int* __restrict__ tokens,
                             const float* __restrict__ emb,
                             float* __restrict__ x) {
    int row = blockIdx.x;
    int tok = tokens[row];
    const float4* src = (const float4*)(emb + (long)tok * N_D);
    float4* dst = (float4*)(x + (long)row * N_D);
    dst[threadIdx.x] = src[threadIdx.x];      // 256 threads * float4 = 1024
}

// mask bias: nb[b,k] = (tokens[b,k]==0) ? -inf : 0
__global__ void mask_kernel(const int* __restrict__ tokens, float* __restrict__ nb) {
    int i = blockIdx.x * blockDim.x + threadIdx.x;
    nb[i] = (tokens[i] == 0) ? -INFINITY : 0.0f;
}

// ---------------------------------------------------------------------------
// Generic fp32 GEMM, 128x128x8 tile, 256 threads, 8x8 microtile.
//   C[M,N] = A[M,K] * op(B) (+bias) (+res)
//   TB=false: B is [K,N] (NN).  TB=true: B is [N,K] (NT, i.e. C=A*B^T).
//   Batched via blockIdx.z strides. All dims multiples of 128 (K mult of 8).
// ---------------------------------------------------------------------------
template <bool TB, bool BIAS, bool RES>
__global__ void __launch_bounds__(256)
gemm128(const float* __restrict__ A, const float* __restrict__ B,
        const float* __restrict__ bias, const float* __restrict__ res,
        float* __restrict__ C, int M, int N, int K,
        long sA, long sB, long sC) {
    __shared__ float As[8][128];
    __shared__ float Bs[8][128];

    int tid = threadIdx.x;
    A += (long)blockIdx.z * sA;
    B += (long)blockIdx.z * sB;
    C += (long)blockIdx.z * sC;
    int row0 = blockIdx.y * 128;
    int col0 = blockIdx.x * 128;

    int a_r  = tid >> 1;
    int a_k4 = (tid & 1) * 4;
    int b_k, b_c;
    if (!TB) { b_k = tid >> 5; b_c = (tid & 31) * 4; }
    else     { b_c = tid >> 1; b_k = (tid & 1) * 4; }

    int tx = tid & 15, ty = tid >> 4;

    float acc[8][8];
    #pragma unroll
    for (int i = 0; i < 8; i++)
        #pragma unroll
        for (int j = 0; j < 8; j++) acc[i][j] = 0.0f;

    for (int k0 = 0; k0 < K; k0 += 8) {
        float4 av = *(const float4*)(A + (long)(row0 + a_r) * K + k0 + a_k4);
        As[a_k4 + 0][a_r] = av.x;
        As[a_k4 + 1][a_r] = av.y;
        As[a_k4 + 2][a_r] = av.z;
        As[a_k4 + 3][a_r] = av.w;
        if (!TB) {
            float4 bv = *(const float4*)(B + (long)(k0 + b_k) * N + col0 + b_c);
            *(float4*)&Bs[b_k][b_c] = bv;
        } else {
            float4 bv = *(const float4*)(B + (long)(col0 + b_c) * K + k0 + b_k);
            Bs[b_k + 0][b_c] = bv.x;
            Bs[b_k + 1][b_c] = bv.y;
            Bs[b_k + 2][b_c] = bv.z;
            Bs[b_k + 3][b_c] = bv.w;
        }
        __syncthreads();
        #pragma unroll
        for (int kk = 0; kk < 8; kk++) {
            float a[8], b[8];
            *(float4*)(a + 0) = *(const float4*)&As[kk][ty * 8 + 0];
            *(float4*)(a + 4) = *(const float4*)&As[kk][ty * 8 + 4];
            *(float4*)(b + 0) = *(const float4*)&Bs[kk][tx * 8 + 0];
            *(float4*)(b + 4) = *(const float4*)&Bs[kk][tx * 8 + 4];
            #pragma unroll
            for (int i = 0; i < 8; i++)
                #pragma unroll
                for (int j = 0; j < 8; j++) acc[i][j] += a[i] * b[j];
        }
        __syncthreads();
    }

    #pragma unroll
    for (int i = 0; i < 8; i++) {
        int r = row0 + ty * 8 + i;
        #pragma unroll
        for (int j = 0; j < 8; j += 4) {
            int c = col0 + tx * 8 + j;
            float4 v = make_float4(acc[i][j], acc[i][j + 1], acc[i][j + 2], acc[i][j + 3]);
            if (BIAS) {
                float4 bb = *(const float4*)(bias + c);
                v.x += bb.x; v.y += bb.y; v.z += bb.z; v.w += bb.w;
            }
            if (RES) {
                float4 rr = *(const float4*)(res + (long)r * N + c);
                v.x += rr.x; v.y += rr.y; v.z += rr.z; v.w += rr.w;
            }
            *(float4*)(C + (long)r * N + c) = v;
        }
    }
}

// ---------------------------------------------------------------------------
// Softmax over score rows, applying SCALE and the (faithful) bh%8 key mask.
//   S[bh, q, :1024] -> softmax in-place.  grid (1024 q, 64 bh), 256 threads
// ---------------------------------------------------------------------------
__global__ void __launch_bounds__(256)
softmax_kernel(float* __restrict__ S, const float* __restrict__ nb) {
    int bh = blockIdx.y, q = blockIdx.x, tid = threadIdx.x;
    float* row = S + ((long)bh << 20) + ((long)q << 10);
    const float* nbr = nb + ((bh & 7) << 10);

    float vals[4];
    float mx = -INFINITY;
    #pragma unroll
    for (int i = 0; i < 4; i++) {
        int k = tid + i * 256;
        float v = row[k] * SCALE_F + nbr[k];
        vals[i] = v;
        mx = fmaxf(mx, v);
    }
    mx = blockMax(mx);
    float sum = 0.0f;
    #pragma unroll
    for (int i = 0; i < 4; i++) {
        vals[i] = expf(vals[i] - mx);   // exp(-inf)=0 for masked keys
        sum += vals[i];
    }
    sum = blockSum(sum);
    float inv = 1.0f / sum;
    #pragma unroll
    for (int i = 0; i < 4; i++) row[tid + i * 256] = vals[i] * inv;
}

// ---------------------------------------------------------------------------
// Pooling: agg[b, d] = max_l r[b,l,d]; agg[b, D+d] = mean_l r[b,l,d]
//   grid (8 b, 8 dchunk), 128 threads
// ---------------------------------------------------------------------------
__global__ void pool_kernel(const float* __restrict__ r, float* __restrict__ agg) {
    int b = blockIdx.x;
    int d = blockIdx.y * 128 + threadIdx.x;
    const float* base = r + ((long)b << 20) + d;
    float mx = -INFINITY, sm = 0.0f;
    #pragma unroll 4
    for (int l = 0; l < N_L; l++) {
        float v = base[(long)l << 10];
        mx = fmaxf(mx, v);
        sm += v;
    }
    agg[b * 2048 + d]        = mx;
    agg[b * 2048 + 1024 + d] = sm * (1.0f / 1024.0f);
}

// ---------------------------------------------------------------------------
// LayerNorm over 2048 dims (population variance), one block per batch row
// ---------------------------------------------------------------------------
__global__ void __launch_bounds__(256)
ln_kernel(const float* __restrict__ agg, const float* __restrict__ gamma,
          const float* __restrict__ beta, float* __restrict__ out) {
    int b = blockIdx.x, tid = threadIdx.x;
    const float* a = agg + b * 2048;
    float s = 0.0f;
    #pragma unroll
    for (int i = 0; i < 8; i++) s += a[tid + i * 256];
    s = blockSum(s);
    float mu = s * (1.0f / 2048.0f);
    float vs = 0.0f;
    #pragma unroll
    for (int i = 0; i < 8; i++) {
        float d = a[tid + i * 256] - mu;
        vs += d * d;
    }
    vs = blockSum(vs);
    float inv = rsqrtf(vs * (1.0f / 2048.0f) + EPS_F);
    #pragma unroll
    for (int i = 0; i < 8; i++) {
        int k = tid + i * 256;
        out[b * 2048 + k] = (a[k] - mu) * inv * gamma[k] + beta[k];
    }
}

// ---------------------------------------------------------------------------
// Launch
// ---------------------------------------------------------------------------
extern "C" void kernel_launch(void* const* d_in, const int* in_sizes, int n_in,
                              void* d_out, int out_size) {
    const int*   tokens = (const int*)  d_in[0];
    const float* emb    = (const float*)d_in[1];
    const float* Wq     = (const float*)d_in[2];
    const float* bq     = (const float*)d_in[3];
    const float* Wk     = (const float*)d_in[4];
    const float* bk     = (const float*)d_in[5];
    const float* Wv     = (const float*)d_in[6];
    const float* bv     = (const float*)d_in[7];
    const float* Wo     = (const float*)d_in[8];
    const float* bo     = (const float*)d_in[9];
    const float* gamma  = (const float*)d_in[10];
    const float* beta   = (const float*)d_in[11];
    float* out = (float*)d_out;

    float *x, *q, *k, *v, *c, *s, *nb, *agg;
    cudaGetSymbolAddress((void**)&x,   g_x);
    cudaGetSymbolAddress((void**)&q,   g_q);
    cudaGetSymbolAddress((void**)&k,   g_k);
    cudaGetSymbolAddress((void**)&v,   g_v);
    cudaGetSymbolAddress((void**)&c,   g_c);
    cudaGetSymbolAddress((void**)&s,   g_s);
    cudaGetSymbolAddress((void**)&nb,  g_nb);
    cudaGetSymbolAddress((void**)&agg, g_agg);

    // 1. embed + mask
    embed_kernel<<<N_B * N_L, 256>>>(tokens, emb, x);
    mask_kernel<<<8, 1024>>>(tokens, nb);

    // 2. Q/K/V projections: [8192,1024] x [1024,1024] + bias
    dim3 gProj(8, 64, 1);
    gemm128<false, true, false><<<gProj, 256>>>(x, Wq, bq, nullptr, q, 8192, 1024, 1024, 0, 0, 0);
    gemm128<false, true, false><<<gProj, 256>>>(x, Wk, bk, nullptr, k, 8192, 1024, 1024, 0, 0, 0);
    gemm128<false, true, false><<<gProj, 256>>>(x, Wv, bv, nullptr, v, 8192, 1024, 1024, 0, 0, 0);

    // 3. scores = Q K^T (batched over 64 flat heads); scale+mask applied in softmax
    dim3 gS(8, 8, 64);
    gemm128<true, false, false><<<gS, 256>>>(q, k, nullptr, nullptr, s,
                                             1024, 1024, 128,
                                             131072L, 131072L, 1048576L);

    // 4. softmax rows (scale 0.25, mask batch = bh % 8, faithful to reference)
    softmax_kernel<<<dim3(1024, 64), 256>>>(s, nb);

    // 5. ctx = P V
    dim3 gPV(1, 8, 64);
    gemm128<false, false, false><<<gPV, 256>>>(s, v, nullptr, nullptr, c,
                                               1024, 128, 1024,
                                               1048576L, 131072L, 131072L);

    // 6. r = x + ctx @ Wo + bo   (store into g_q, which is free now)
    gemm128<false, true, true><<<gProj, 256>>>(c, Wo, bo, x, q, 8192, 1024, 1024, 0, 0, 0);

    // 7. max/mean pool over L
    pool_kernel<<<dim3(8, 8), 128>>>(q, agg);

    // 8. layernorm -> output [8, 2048]
    ln_kernel<<<8, 256>>>(agg, gamma, beta, out);
}

// round 4
// speedup vs baseline: 1.0022x; 1.0022x over previous
#include <cuda_runtime.h>
#include <math.h>

// Shapes (fixed for this problem)
//  B=8, L=1024, D=1024, H=8, DH=128, BH=64, VOCAB=32000
//  SCALE = (DH//H)^-0.5 = 0.25
//  Output: [8, 2048] f32 layernorm of [maxpool | meanpool]

#define N_B    8
#define N_L    1024
#define N_D    1024
#define N_BH   64
#define N_DH   128
#define SCALE_F 0.25f
#define EPS_F   1e-5f

// ---------------------------------------------------------------------------
// Scratch (static __device__ arrays; no allocation allowed)
// ---------------------------------------------------------------------------
__device__ float g_x[8u * 1024u * 1024u];   // embedded input  [B,L,D]
__device__ float g_q[8u * 1024u * 1024u];   // Q, later reused as r = x + out
__device__ float g_k[8u * 1024u * 1024u];   // K
__device__ float g_v[8u * 1024u * 1024u];   // V
__device__ float g_c[8u * 1024u * 1024u];   // ctx
__device__ float g_s[67108864u];            // scores/probs [64,1024,1024] (256MB)
__device__ float g_nb[8 * 1024];            // -inf mask bias per (batch,key)
__device__ float g_agg[8 * 2048];           // pooled features

// ---------------------------------------------------------------------------
// Block reductions
// ---------------------------------------------------------------------------
__device__ __forceinline__ float blockSum(float v) {
    __shared__ float sh[32];
    int lane = threadIdx.x & 31, wid = threadIdx.x >> 5;
    #pragma unroll
    for (int o = 16; o > 0; o >>= 1) v += __shfl_xor_sync(0xffffffffu, v, o);
    if (lane == 0) sh[wid] = v;
    __syncthreads();
    int nw = blockDim.x >> 5;
    float r = (threadIdx.x < (unsigned)nw) ? sh[threadIdx.x] : 0.0f;
    if (wid == 0) {
        #pragma unroll
        for (int o = 16; o > 0; o >>= 1) r += __shfl_xor_sync(0xffffffffu, r, o);
        if (lane == 0) sh[0] = r;
    }
    __syncthreads();
    float out = sh[0];
    __syncthreads();
    return out;
}

__device__ __forceinline__ float blockMax(float v) {
    __shared__ float sh[32];
    int lane = threadIdx.x & 31, wid = threadIdx.x >> 5;
    #pragma unroll
    for (int o = 16; o > 0; o >>= 1) v = fmaxf(v, __shfl_xor_sync(0xffffffffu, v, o));
    if (lane == 0) sh[wid] = v;
    __syncthreads();
    int nw = blockDim.x >> 5;
    float r = (threadIdx.x < (unsigned)nw) ? sh[threadIdx.x] : -INFINITY;
    if (wid == 0) {
        #pragma unroll
        for (int o = 16; o > 0; o >>= 1) r = fmaxf(r, __shfl_xor_sync(0xffffffffu, r, o));
        if (lane == 0) sh[0] = r;
    }
    __syncthreads();
    float out = sh[0];
    __syncthreads();
    return out;
}

// ---------------------------------------------------------------------------
// Embedding gather: x[row,:] = emb[tok[row],:]   (8192 rows x 1024 f32)
// ---------------------------------------------------------------------------
__global__ void embed_kernel(const int* __restrict__ tokens,
                             const float* __restrict__ emb,
                             float* __restrict__ x) {
    int row = blockIdx.x;
    int tok = tokens[row];
    const float4* src = (const float4*)(emb + (long)tok * N_D);
    float4* dst = (float4*)(x + (long)row * N_D);
    dst[threadIdx.x] = src[threadIdx.x];      // 256 threads * float4 = 1024
}

// mask bias: nb[b,k] = (tokens[b,k]==0) ? -inf : 0
__global__ void mask_kernel(const int* __restrict__ tokens, float* __restrict__ nb) {
    int i = blockIdx.x * blockDim.x + threadIdx.x;
    nb[i] = (tokens[i] == 0) ? -INFINITY : 0.0f;
}

// ---------------------------------------------------------------------------
// Generic fp32 GEMM, 128x128x8 tile, 256 threads, 8x8 microtile.
//   C[M,N] = A[M,K] * op(B) (+bias) (+res)
//   TB=false: B is [K,N] (NN).  TB=true: B is [N,K] (NT, i.e. C=A*B^T).
//   Batched via blockIdx.z strides. All dims multiples of 128 (K mult of 8).
// ---------------------------------------------------------------------------
template <bool TB, bool BIAS, bool RES>
__global__ void __launch_bounds__(256)
gemm128(const float* __restrict__ A, const float* __restrict__ B,
        const float* __restrict__ bias, const float* __restrict__ res,
        float* __restrict__ C, int M, int N, int K,
        long sA, long sB, long sC) {
    __shared__ float As[8][128];
    __shared__ float Bs[8][128];

    int tid = threadIdx.x;
    A += (long)blockIdx.z * sA;
    B += (long)blockIdx.z * sB;
    C += (long)blockIdx.z * sC;
    int row0 = blockIdx.y * 128;
    int col0 = blockIdx.x * 128;

    int a_r  = tid >> 1;
    int a_k4 = (tid & 1) * 4;
    int b_k, b_c;
    if (!TB) { b_k = tid >> 5; b_c = (tid & 31) * 4; }
    else     { b_c = tid >> 1; b_k = (tid & 1) * 4; }

    int tx = tid & 15, ty = tid >> 4;

    float acc[8][8];
    #pragma unroll
    for (int i = 0; i < 8; i++)
        #pragma unroll
        for (int j = 0; j < 8; j++) acc[i][j] = 0.0f;

    for (int k0 = 0; k0 < K; k0 += 8) {
        float4 av = *(const float4*)(A + (long)(row0 + a_r) * K + k0 + a_k4);
        As[a_k4 + 0][a_r] = av.x;
        As[a_k4 + 1][a_r] = av.y;
        As[a_k4 + 2][a_r] = av.z;
        As[a_k4 + 3][a_r] = av.w;
        if (!TB) {
            float4 bv = *(const float4*)(B + (long)(k0 + b_k) * N + col0 + b_c);
            *(float4*)&Bs[b_k][b_c] = bv;
        } else {
            float4 bv = *(const float4*)(B + (long)(col0 + b_c) * K + k0 + b_k);
            Bs[b_k + 0][b_c] = bv.x;
            Bs[b_k + 1][b_c] = bv.y;
            Bs[b_k + 2][b_c] = bv.z;
            Bs[b_k + 3][b_c] = bv.w;
        }
        __syncthreads();
        #pragma unroll
        for (int kk = 0; kk < 8; kk++) {
            float a[8], b[8];
            *(float4*)(a + 0) = *(const float4*)&As[kk][ty * 8 + 0];
            *(float4*)(a + 4) = *(const float4*)&As[kk][ty * 8 + 4];
            *(float4*)(b + 0) = *(const float4*)&Bs[kk][tx * 8 + 0];
            *(float4*)(b + 4) = *(const float4*)&Bs[kk][tx * 8 + 4];
            #pragma unroll
            for (int i = 0; i < 8; i++)
                #pragma unroll
                for (int j = 0; j < 8; j++) acc[i][j] += a[i] * b[j];
        }
        __syncthreads();
    }

    #pragma unroll
    for (int i = 0; i < 8; i++) {
        int r = row0 + ty * 8 + i;
        #pragma unroll
        for (int j = 0; j < 8; j += 4) {
            int c = col0 + tx * 8 + j;
            float4 v = make_float4(acc[i][j], acc[i][j + 1], acc[i][j + 2], acc[i][j + 3]);
            if (BIAS) {
                float4 bb = *(const float4*)(bias + c);
                v.x += bb.x; v.y += bb.y; v.z += bb.z; v.w += bb.w;
            }
            if (RES) {
                float4 rr = *(const float4*)(res + (long)r * N + c);
                v.x += rr.x; v.y += rr.y; v.z += rr.z; v.w += rr.w;
            }
            *(float4*)(C + (long)r * N + c) = v;
        }
    }
}

// ---------------------------------------------------------------------------
// Softmax over score rows, applying SCALE and the (faithful) bh%8 key mask.
//   S[bh, q, :1024] -> softmax in-place.  grid (1024 q, 64 bh), 256 threads
// ---------------------------------------------------------------------------
__global__ void __launch_bounds__(256)
softmax_kernel(float* __restrict__ S, const float* __restrict__ nb) {
    int bh = blockIdx.y, q = blockIdx.x, tid = threadIdx.x;
    float* row = S + ((long)bh << 20) + ((long)q << 10);
    const float* nbr = nb + ((bh & 7) << 10);

    float vals[4];
    float mx = -INFINITY;
    #pragma unroll
    for (int i = 0; i < 4; i++) {
        int k = tid + i * 256;
        float v = row[k] * SCALE_F + nbr[k];
        vals[i] = v;
        mx = fmaxf(mx, v);
    }
    mx = blockMax(mx);
    float sum = 0.0f;
    #pragma unroll
    for (int i = 0; i < 4; i++) {
        vals[i] = expf(vals[i] - mx);   // exp(-inf)=0 for masked keys
        sum += vals[i];
    }
    sum = blockSum(sum);
    float inv = 1.0f / sum;
    #pragma unroll
    for (int i = 0; i < 4; i++) row[tid + i * 256] = vals[i] * inv;
}

// ---------------------------------------------------------------------------
// Pooling: agg[b, d] = max_l r[b,l,d]; agg[b, D+d] = mean_l r[b,l,d]
//   grid (8 b, 8 dchunk), 128 threads
// ---------------------------------------------------------------------------
__global__ void pool_kernel(const float* __restrict__ r, float* __restrict__ agg) {
    int b = blockIdx.x;
    int d = blockIdx.y * 128 + threadIdx.x;
    const float* base = r + ((long)b << 20) + d;
    float mx = -INFINITY, sm = 0.0f;
    #pragma unroll 4
    for (int l = 0; l < N_L; l++) {
        float v = base[(long)l << 10];
        mx = fmaxf(mx, v);
        sm += v;
    }
    agg[b * 2048 + d]        = mx;
    agg[b * 2048 + 1024 + d] = sm * (1.0f / 1024.0f);
}

// ---------------------------------------------------------------------------
// LayerNorm over 2048 dims (population variance), one block per batch row
// ---------------------------------------------------------------------------
__global__ void __launch_bounds__(256)
ln_kernel(const float* __restrict__ agg, const float* __restrict__ gamma,
          const float* __restrict__ beta, float* __restrict__ out) {
    int b = blockIdx.x, tid = threadIdx.x;
    const float* a = agg + b * 2048;
    float s = 0.0f;
    #pragma unroll
    for (int i = 0; i < 8; i++) s += a[tid + i * 256];
    s = blockSum(s);
    float mu = s * (1.0f / 2048.0f);
    float vs = 0.0f;
    #pragma unroll
    for (int i = 0; i < 8; i++) {
        float d = a[tid + i * 256] - mu;
        vs += d * d;
    }
    vs = blockSum(vs);
    float inv = rsqrtf(vs * (1.0f / 2048.0f) + EPS_F);
    #pragma unroll
    for (int i = 0; i < 8; i++) {
        int k = tid + i * 256;
        out[b * 2048 + k] = (a[k] - mu) * inv * gamma[k] + beta[k];
    }
}

// ---------------------------------------------------------------------------
// Launch
// ---------------------------------------------------------------------------
extern "C" void kernel_launch(void* const* d_in, const int* in_sizes, int n_in,
                              void* d_out, int out_size) {
    const int*   tokens = (const int*)  d_in[0];
    const float* emb    = (const float*)d_in[1];
    const float* Wq     = (const float*)d_in[2];
    const float* bq     = (const float*)d_in[3];
    const float* Wk     = (const float*)d_in[4];
    const float* bk     = (const float*)d_in[5];
    const float* Wv     = (const float*)d_in[6];
    const float* bv     = (const float*)d_in[7];
    const float* Wo     = (const float*)d_in[8];
    const float* bo     = (const float*)d_in[9];
    const float* gamma  = (const float*)d_in[10];
    const float* beta   = (const float*)d_in[11];
    float* out = (float*)d_out;

    float *x, *q, *k, *v, *c, *s, *nb, *agg;
    cudaGetSymbolAddress((void**)&x,   g_x);
    cudaGetSymbolAddress((void**)&q,   g_q);
    cudaGetSymbolAddress((void**)&k,   g_k);
    cudaGetSymbolAddress((void**)&v,   g_v);
    cudaGetSymbolAddress((void**)&c,   g_c);
    cudaGetSymbolAddress((void**)&s,   g_s);
    cudaGetSymbolAddress((void**)&nb,  g_nb);
    cudaGetSymbolAddress((void**)&agg, g_agg);

    // 1. embed + mask
    embed_kernel<<<N_B * N_L, 256>>>(tokens, emb, x);
    mask_kernel<<<8, 1024>>>(tokens, nb);

    // 2. Q/K/V projections: [8192,1024] x [1024,1024] + bias
    dim3 gProj(8, 64, 1);
    gemm128<false, true, false><<<gProj, 256>>>(x, Wq, bq, nullptr, q, 8192, 1024, 1024, 0, 0, 0);
    gemm128<false, true, false><<<gProj, 256>>>(x, Wk, bk, nullptr, k, 8192, 1024, 1024, 0, 0, 0);
    gemm128<false, true, false><<<gProj, 256>>>(x, Wv, bv, nullptr, v, 8192, 1024, 1024, 0, 0, 0);

    // 3. scores = Q K^T (batched over 64 flat heads); scale+mask applied in softmax
    dim3 gS(8, 8, 64);
    gemm128<true, false, false><<<gS, 256>>>(q, k, nullptr, nullptr, s,
                                             1024, 1024, 128,
                                             131072L, 131072L, 1048576L);

    // 4. softmax rows (scale 0.25, mask batch = bh % 8, faithful to reference)
    softmax_kernel<<<dim3(1024, 64), 256>>>(s, nb);

    // 5. ctx = P V
    dim3 gPV(1, 8, 64);
    gemm128<false, false, false><<<gPV, 256>>>(s, v, nullptr, nullptr, c,
                                               1024, 128, 1024,
                                               1048576L, 131072L, 131072L);

    // 6. r = x + ctx @ Wo + bo   (store into g_q, which is free now)
    gemm128<false, true, true><<<gProj, 256>>>(c, Wo, bo, x, q, 8192, 1024, 1024, 0, 0, 0);

    // 7. max/mean pool over L
    pool_kernel<<<dim3(8, 8), 128>>>(q, agg);

    // 8. layernorm -> output [8, 2048]
    ln_kernel<<<8, 256>>>(agg, gamma, beta, out);
}